// round 17
// baseline (speedup 1.0000x reference)
#include <cuda_runtime.h>
#include <cuda_fp16.h>
#include <cstdint>

// conv_layer_65000035058096 — 2xFP16 mma.sync gather-GEMM (baseline PTX)
// D = x_fp16*wh + x_fp16*wl (W split fp16 hi+lo; x rounded to fp16 ONCE in a
// prepass plane -> gather bytes halve, zero cvt in the hot loop).
// R17 = R16 champion + fp16 x-plane prepass. rel_err unchanged ~2.1e-4.

#define V_TOT 163842
#define NCH 28            // k-steps of 16
#define TILE_V 256
#define SAW 12            // A row stride in words (8 data + 4 pad) -> conflict-free

// B fragments, mma m16n8k16 register layout, wh/wl packed:
// g_Bf[(s*8+nb)*32 + lane] = {wh0, wh1, wl0, wl1}
__device__ uint4 g_Bf[NCH * 8 * 32];
// x as fp16 plane: 8 fp16 per uint4;  2*V*64/8 entries
#define NX8 2621472
__device__ uint4 g_xh[NX8];

__device__ __forceinline__ uint32_t pack_f16x2(float hi_elem, float lo_elem) {
    uint32_t r;
    asm("cvt.rn.f16x2.f32 %0, %1, %2;" : "=r"(r) : "f"(hi_elem), "f"(lo_elem));
    return r;
}

__global__ void pack_B_kernel(const float* __restrict__ W) {
    int idx = blockIdx.x * blockDim.x + threadIdx.x;   // 7168
    if (idx < NCH * 8 * 32) {
        int l = idx & 31, nbk = (idx >> 5) & 7, s = idx >> 8;
        int g = l >> 2, tig = l & 3;
        int o = nbk * 8 + g;
        const float* wr = W + o * 448 + s * 16 + 2 * tig;
        float v[4] = { wr[0], wr[1], wr[8], wr[9] };
        float h[4], lo[4];
#pragma unroll
        for (int i = 0; i < 4; ++i) {
            __half hb = __float2half_rn(v[i]);
            h[i] = __half2float(hb);
            lo[i] = v[i] - h[i];
        }
        uint4 r;
        r.x = pack_f16x2(h[1], h[0]);
        r.y = pack_f16x2(h[3], h[2]);
        r.z = pack_f16x2(lo[1], lo[0]);
        r.w = pack_f16x2(lo[3], lo[2]);
        g_Bf[idx] = r;
    }
}

__global__ void cvt_x_kernel(const float* __restrict__ x) {
    int i = blockIdx.x * blockDim.x + threadIdx.x;
    if (i < NX8) {
        const float4 v0 = reinterpret_cast<const float4*>(x)[2 * i];
        const float4 v1 = reinterpret_cast<const float4*>(x)[2 * i + 1];
        uint4 h;
        h.x = pack_f16x2(v0.y, v0.x);
        h.y = pack_f16x2(v0.w, v0.z);
        h.z = pack_f16x2(v1.y, v1.x);
        h.w = pack_f16x2(v1.w, v1.z);
        g_xh[i] = h;
    }
}

__device__ __forceinline__ void cpa16(uint32_t dst, const void* src) {
    asm volatile("cp.async.cg.shared.global [%0], [%1], 16;" :: "r"(dst), "l"(src) : "memory");
}
__device__ __forceinline__ uint32_t smem_u32(const void* p) {
    uint32_t a;
    asm("{ .reg .u64 t; cvta.to.shared.u64 t, %1; cvt.u32.u64 %0, t; }" : "=r"(a) : "l"(p));
    return a;
}
#define MMA(c, a, b0, b1) asm volatile( \
    "mma.sync.aligned.m16n8k16.row.col.f32.f16.f16.f32 " \
    "{%0,%1,%2,%3}, {%4,%5,%6,%7}, {%8,%9}, {%0,%1,%2,%3};" \
    : "+f"((c)[0]), "+f"((c)[1]), "+f"((c)[2]), "+f"((c)[3]) \
    : "r"((a)[0]), "r"((a)[1]), "r"((a)[2]), "r"((a)[3]), "r"(b0), "r"(b1))

__global__ __launch_bounds__(256, 2)
void sconv_f16(const int* __restrict__ nb,
               const float* __restrict__ bias,
               float* __restrict__ out) {
    __shared__ uint32_t As[2][TILE_V * SAW];   // 2 x 12288 B, fp16 rows (16 k ea)
    __shared__ uint4    Bs[2][256];            // 2 x 4096 B
    __shared__ int      nbs[7 * TILE_V];       // 7168 B   -> 39936 B static total

    const int t    = threadIdx.x;
    const int lane = t & 31;
    const int w    = t >> 5;
    const int g    = lane >> 2;
    const int tig  = lane & 3;
    const int wv   = w << 5;            // warp vertex base (32 v per warp)
    const int batch = blockIdx.y;
    const int v0    = blockIdx.x * TILE_V;
    const long long xbase = (long long)batch * V_TOT;
    const char* xh = (const char*)g_xh;       // vertex row = 128 B fp16
    const char* gB = (const char*)g_Bf;

    // ---- stage neighbor indices: nbs[j*256 + r]
#pragma unroll
    for (int i = 0; i < 7; ++i) {
        int idx = t + (i << 8);
        int r = idx & 255, j = idx >> 8;
        int vv = v0 + r; if (vv >= V_TOT) vv = V_TOT - 1;
        nbs[idx] = nb[vv * 7 + j];
    }
    __syncthreads();

    const uint32_t asb[2] = { smem_u32(&As[0][0]), smem_u32(&As[1][0]) };
    const uint32_t bsb[2] = { smem_u32(&Bs[0][0]), smem_u32(&Bs[1][0]) };

    float acc[2][8][4];
#pragma unroll
    for (int rb = 0; rb < 2; ++rb)
#pragma unroll
        for (int n = 0; n < 8; ++n)
#pragma unroll
            for (int e = 0; e < 4; ++e) acc[rb][n][e] = 0.0f;

    // prologue: stage chunk 0 (j=0, kb=0); thread t stages row t (32 B)
    {
        const char* src = xh + ((xbase + nbs[t]) << 7);
        const uint32_t dst = asb[0] + t * 48;
        cpa16(dst,      src);
        cpa16(dst + 16, src + 16);
        cpa16(bsb[0] + t * 16, gB + t * 16);
        asm volatile("cp.async.commit_group;" ::: "memory");
    }

    for (int c = 0; c < NCH; ++c) {
        const int buf = c & 1;

        if (c + 1 < NCH) {
            const int cn = c + 1;
            const int j  = cn >> 2;
            const int kB = (cn & 3) << 5;     // byte offset within 128-B fp16 row
            const int bn = cn & 1;
            const char* src = xh + ((xbase + nbs[j * 256 + t]) << 7) + kB;
            const uint32_t dst = asb[bn] + t * 48;
            cpa16(dst,      src);
            cpa16(dst + 16, src + 16);
            cpa16(bsb[bn] + t * 16, gB + cn * 4096 + t * 16);
            asm volatile("cp.async.commit_group;" ::: "memory");
            asm volatile("cp.async.wait_group 1;" ::: "memory");
        } else {
            asm volatile("cp.async.wait_group 0;" ::: "memory");
        }
        __syncthreads();

        // ---- compute chunk c: 8 LDS.32 (A frags) + 8 LDS.128 (B) + 32 MMA
        const uint32_t* aB = &As[buf][0];
        uint32_t af[2][4];
#pragma unroll
        for (int rb = 0; rb < 2; ++rb) {
            const int r0 = (wv + (rb << 4) + g) * SAW;
            const int r1 = r0 + 8 * SAW;
            af[rb][0] = aB[r0 + tig];
            af[rb][1] = aB[r1 + tig];
            af[rb][2] = aB[r0 + tig + 4];
            af[rb][3] = aB[r1 + tig + 4];
        }

        const uint4* bB = &Bs[buf][0];
#pragma unroll
        for (int nblk = 0; nblk < 8; ++nblk) {
            uint4 bf = bB[(nblk << 5) + lane];
            MMA(acc[0][nblk], af[0], bf.x, bf.y);   // x * wh
            MMA(acc[1][nblk], af[1], bf.x, bf.y);
            MMA(acc[0][nblk], af[0], bf.z, bf.w);   // x * wl
            MMA(acc[1][nblk], af[1], bf.z, bf.w);
        }
        __syncthreads();   // done reading buf before it is re-staged
    }

    // ---- epilogue: D frags -> global (+bias)
#pragma unroll
    for (int rb = 0; rb < 2; ++rb) {
        const int vr0 = v0 + wv + (rb << 4) + g;
        const int vr1 = vr0 + 8;
#pragma unroll
        for (int nblk = 0; nblk < 8; ++nblk) {
            const int n = (nblk << 3) + 2 * tig;
            const float2 b2 = *reinterpret_cast<const float2*>(bias + n);
            if (vr0 < V_TOT)
                *reinterpret_cast<float2*>(out + ((xbase + vr0) << 6) + n) =
                    make_float2(acc[rb][nblk][0] + b2.x, acc[rb][nblk][1] + b2.y);
            if (vr1 < V_TOT)
                *reinterpret_cast<float2*>(out + ((xbase + vr1) << 6) + n) =
                    make_float2(acc[rb][nblk][2] + b2.x, acc[rb][nblk][3] + b2.y);
        }
    }
}

extern "C" void kernel_launch(void* const* d_in, const int* in_sizes, int n_in,
                              void* d_out, int out_size) {
    const float* x   = (const float*)d_in[0];   // (2, V, 64) f32
    const int*   nbi = (const int*)d_in[1];     // (V*7,) i32
    const float* W   = (const float*)d_in[2];   // (64, 448) f32
    const float* b   = (const float*)d_in[3];   // (64,) f32
    float*       out = (float*)d_out;           // (2, V, 64) f32

    pack_B_kernel<<<(NCH * 8 * 32 + 255) / 256, 256>>>(W);
    cvt_x_kernel<<<(NX8 + 255) / 256, 256>>>(x);

    dim3 grid((V_TOT + TILE_V - 1) / TILE_V, 2);
    sconv_f16<<<grid, 256>>>(nbi, b, out);
}